// round 9
// baseline (speedup 1.0000x reference)
#include <cuda_runtime.h>
#include <cuda_fp16.h>
#include <cstdint>
#include <cstddef>

#define DI __device__ __forceinline__

#define BATCH 1024
#define NF    32
#define NPAIR 496
#define T_LD  1984
#define X_LD  2048
#define HALFK 31744
#define KTOT  63488
#define NKT   1984               // KTOT/32 k-tiles
#define H1    1024
#define H2    512

// ---- fragment-layout GEMM (fc0): BM=128, BN=128, BK=32, 8 warps (2x4), warp tile 64x32.
// A tile = 8 atom_m x 2 atom_k x 32 lanes x 16B = 8192B (fragment order).
// B tile = 16 atom_n x 2 atom_k x 32 lanes x 8B  = 8192B.
#define FTILE_B 8192
#define NSTAGE 3
#define SMEM_FRAG (NSTAGE*2*FTILE_B)   // 49152

// ---- row-major GEMM (fc1) constants (verified R5/R7 path)
#define SROWB 80
#define TBUFH_BYTES (128*SROWB)
#define SMEM_RM (2*NSTAGE*TBUFH_BYTES) // 61440

__device__ float  g_x2[BATCH*X_LD];
__device__ float  g_T[2*BATCH*T_LD];
__device__ __half g_feat[(size_t)BATCH*KTOT];   // fragment-order features (130MB)
__device__ __half g_w0f[(size_t)H1*KTOT];       // fragment-order fc0 weights (130MB)
__device__ __half g_w1h[H2*H1];
__device__ float  g_part0[4*BATCH*H1];
__device__ __half g_h0h[BATCH*H1];
__device__ float  g_part1[4*BATCH*H2];
__device__ float  g_h1[BATCH*H2];
__device__ int    g_pi[NPAIR];
__device__ int    g_pj[NPAIR];

DI uint32_t smem_u32(const void* p) {
    uint32_t a;
    asm("{ .reg .u64 t; cvta.to.shared.u64 t, %1; cvt.u32.u64 %0, t; }" : "=r"(a) : "l"(p));
    return a;
}

DI void cp_async16(uint32_t dst, const void* src) {
    asm volatile("cp.async.cg.shared.global [%0], [%1], 16;" :: "r"(dst), "l"(src));
}
#define CP_COMMIT() asm volatile("cp.async.commit_group;" ::: "memory")
#define CP_WAIT1()  asm volatile("cp.async.wait_group 1;" ::: "memory")

DI void mma_f16(float* d, const uint32_t* a, const uint32_t* b) {
    asm volatile(
        "mma.sync.aligned.m16n8k16.row.col.f32.f16.f16.f32 "
        "{%0,%1,%2,%3}, {%4,%5,%6,%7}, {%8,%9}, {%0,%1,%2,%3};"
        : "+f"(d[0]), "+f"(d[1]), "+f"(d[2]), "+f"(d[3])
        : "r"(a[0]), "r"(a[1]), "r"(a[2]), "r"(a[3]), "r"(b[0]), "r"(b[1]));
}

DI uint32_t pack_h2(float a, float b) {
    __half2 h = __floats2half2_rn(a, b);
    return *(uint32_t*)&h;
}

// ---------------- convert fp32 -> fp16 (linear, for fc1 weights) ----------------
__global__ void __launch_bounds__(256) f2h_kernel(const float* __restrict__ src,
                                                  __half* __restrict__ dst, int n4) {
    int i = blockIdx.x * 256 + threadIdx.x;
    if (i < n4) {
        float4 v = ((const float4*)src)[i];
        uint2 o;
        o.x = pack_h2(v.x, v.y);
        o.y = pack_h2(v.z, v.w);
        ((uint2*)dst)[i] = o;
    }
}

// ---------------- small kernels ----------------
__global__ void init_pairs_kernel() {
    if (threadIdx.x == 0) {
        int idx = 0;
        for (int i = 0; i < NF - 1; i++)
            for (int j = i + 1; j < NF; j++) { g_pi[idx] = i; g_pj[idx] = j; idx++; }
    }
}

__global__ void __launch_bounds__(256) se_kernel(const float* __restrict__ x,
                                                 const float* __restrict__ w1,
                                                 const float* __restrict__ w2) {
    __shared__ float xs[X_LD];
    __shared__ float Zs[NF], A1s[4], A2s[NF];
    int b = blockIdx.x, tid = threadIdx.x;
    const float4* xr = (const float4*)(x + (size_t)b * X_LD);
    float4* xs4 = (float4*)xs;
    xs4[tid] = xr[tid];
    xs4[tid + 256] = xr[tid + 256];
    __syncthreads();
    int wid = tid >> 5, lane = tid & 31;
    #pragma unroll
    for (int ff = 0; ff < 4; ff++) {
        int f = wid * 4 + ff;
        float v = xs[f * 64 + lane] + xs[f * 64 + 32 + lane];
        #pragma unroll
        for (int o = 16; o; o >>= 1) v += __shfl_xor_sync(0xffffffffu, v, o);
        if (lane == 0) Zs[f] = v * (1.0f / 64.0f);
    }
    __syncthreads();
    if (tid < 4) {
        float a = 0.f;
        #pragma unroll
        for (int f = 0; f < NF; f++) a += Zs[f] * w1[tid * NF + f];
        A1s[tid] = fmaxf(a, 0.0f);
    }
    __syncthreads();
    if (tid < NF) {
        float a = 0.f;
        #pragma unroll
        for (int r = 0; r < 4; r++) a += A1s[r] * w2[tid * 4 + r];
        A2s[tid] = 1.0f / (1.0f + expf(-a));
    }
    __syncthreads();
    float4* o4 = (float4*)(g_x2 + (size_t)b * X_LD);
    #pragma unroll
    for (int q = 0; q < 2; q++) {
        int i = tid + q * 256;
        float4 v = xs4[i];
        float sc = A2s[i >> 4];
        v.x *= sc; v.y *= sc; v.z *= sc; v.w *= sc;
        o4[i] = v;
    }
}

// t[v][b][i*64+o] = sum_e feats_v[b,i,e] * W_v[i,o,e]
__global__ void __launch_bounds__(256) tfield_kernel(const float* __restrict__ x,
                                                     const float* __restrict__ W1,
                                                     const float* __restrict__ W2) {
    __shared__ float Ws[64 * 68];
    __shared__ float xs[16 * 68];
    __shared__ float ts[1024];
    int v = blockIdx.z, fi = blockIdx.x, b0 = blockIdx.y * 16;
    int tid = threadIdx.x;
    const float* W = (v ? W2 : W1) + (size_t)fi * 4096;
    for (int idx = tid; idx < 4096; idx += 256)
        Ws[(idx >> 6) * 68 + (idx & 63)] = W[idx];
    const float* xsrc = (v ? g_x2 : x) + (size_t)b0 * X_LD + fi * 64;
    for (int idx = tid; idx < 1024; idx += 256)
        xs[(idx >> 6) * 68 + (idx & 63)] = xsrc[(size_t)(idx >> 6) * X_LD + (idx & 63)];
    __syncthreads();
    int o = tid >> 2, bg = tid & 3;
    float s0 = 0.f, s1 = 0.f, s2 = 0.f, s3 = 0.f;
    const float4* wrow = (const float4*)(Ws + o * 68);
    #pragma unroll
    for (int e4 = 0; e4 < 16; e4++) {
        float4 wv = wrow[e4];
        float4 a0 = *(const float4*)(xs + (bg * 4 + 0) * 68 + e4 * 4);
        float4 a1 = *(const float4*)(xs + (bg * 4 + 1) * 68 + e4 * 4);
        float4 a2 = *(const float4*)(xs + (bg * 4 + 2) * 68 + e4 * 4);
        float4 a3 = *(const float4*)(xs + (bg * 4 + 3) * 68 + e4 * 4);
        s0 += wv.x*a0.x + wv.y*a0.y + wv.z*a0.z + wv.w*a0.w;
        s1 += wv.x*a1.x + wv.y*a1.y + wv.z*a1.z + wv.w*a1.w;
        s2 += wv.x*a2.x + wv.y*a2.y + wv.z*a2.z + wv.w*a2.w;
        s3 += wv.x*a3.x + wv.y*a3.y + wv.z*a3.z + wv.w*a3.w;
    }
    ts[(bg * 4 + 0) * 64 + o] = s0;
    ts[(bg * 4 + 1) * 64 + o] = s1;
    ts[(bg * 4 + 2) * 64 + o] = s2;
    ts[(bg * 4 + 3) * 64 + o] = s3;
    __syncthreads();
    float* trow = g_T + (size_t)v * (BATCH * T_LD);
    for (int idx = tid; idx < 1024; idx += 256)
        trow[(size_t)(b0 + (idx >> 6)) * T_LD + fi * 64 + (idx & 63)] = ts[idx];
}

// ---------------- feat materialization in FRAGMENT layout ----------------
// feat tile (mb, kt) = 8192B: slot s = atom_m*64 + atom_k*32 + lane, each slot 16B =
//   {(m, kh), (m+8, kh), (m, kh+8), (m+8, kh+8)} as half2 pairs, where
//   m = atom_m*16 + lane/4, kh = atom_k*16 + (lane%4)*2 (within-tile indices).
// grid (2, NKT, 8), block 256: s = bx*256+tid.
__global__ void __launch_bounds__(256) featgen_kernel(const float* __restrict__ x) {
    int kt = blockIdx.y, mb = blockIdx.z;
    int s = blockIdx.x * 256 + threadIdx.x;
    int atom_m = s >> 6, rest = s & 63;
    int atom_k = rest >> 5, lane = rest & 31;
    int m = atom_m * 16 + (lane >> 2);
    int kh = atom_k * 16 + (lane & 3) * 2;
    int kg = kt * 32 + kh;
    int v = (kg >= HALFK) ? 1 : 0;
    int rem = kg - v * HALFK;
    int p = rem >> 6, e = rem & 63;
    int ip = g_pi[p], jp = g_pj[p];
    int b = mb * 128 + m;
    const float* tb = g_T + (size_t)v * (BATCH * T_LD) + (size_t)b * T_LD + ip * 64 + e;
    const float* xb = (v ? g_x2 : x) + (size_t)b * X_LD + jp * 64 + e;
    const float* tb8 = tb + 8 * T_LD;
    const float* xb8 = xb + 8 * X_LD;
    float2 t00 = *(const float2*)tb,       x00 = *(const float2*)xb;
    float2 t10 = *(const float2*)tb8,      x10 = *(const float2*)xb8;
    float2 t01 = *(const float2*)(tb + 8), x01 = *(const float2*)(xb + 8);
    float2 t11 = *(const float2*)(tb8 + 8), x11 = *(const float2*)(xb8 + 8);
    uint4 o;
    o.x = pack_h2(t00.x * x00.x, t00.y * x00.y);
    o.y = pack_h2(t10.x * x10.x, t10.y * x10.y);
    o.z = pack_h2(t01.x * x01.x, t01.y * x01.y);
    o.w = pack_h2(t11.x * x11.x, t11.y * x11.y);
    *(uint4*)(g_feat + ((size_t)mb * NKT + kt) * 4096 + (size_t)s * 8) = o;
}

// ---------------- fc0 weight permute into FRAGMENT layout ----------------
// w tile (nb, kt) = 8192B: slot s = atom_n*64 + atom_k*32 + lane, each slot 8B =
//   {(n, kh), (n, kh+8)}, n = atom_n*8 + lane/4, kh = atom_k*16 + (lane%4)*2.
// grid (4, NKT, 8), block 256.
__global__ void __launch_bounds__(256) w0frag_kernel(const float* __restrict__ w) {
    int kt = blockIdx.y, nb = blockIdx.z;
    int s = blockIdx.x * 256 + threadIdx.x;
    int atom_n = s >> 6, rest = s & 63;
    int atom_k = rest >> 5, lane = rest & 31;
    int n = nb * 128 + atom_n * 8 + (lane >> 2);
    int kg = kt * 32 + atom_k * 16 + (lane & 3) * 2;
    const float* wsrc = w + (size_t)n * KTOT + kg;
    float2 w0 = *(const float2*)wsrc;
    float2 w1 = *(const float2*)(wsrc + 8);
    uint2 o;
    o.x = pack_h2(w0.x, w0.y);
    o.y = pack_h2(w1.x, w1.y);
    *(uint2*)(g_w0f + ((size_t)nb * NKT + kt) * 4096 + (size_t)s * 4) = o;
}

// ---------------- fc0 GEMM: fragment layout, pure cp.async, 3-stage ----------------
__global__ void __launch_bounds__(256, 2) gemm_frag_kernel(const __half* __restrict__ Af,
                                                           const __half* __restrict__ Bf,
                                                           float* __restrict__ Cpart, int S) {
    extern __shared__ char smc[];
    uint32_t smb = smem_u32(smc);
    int tid = threadIdx.x;
    int w = tid >> 5, l = tid & 31;
    int wr = w >> 2, wc = w & 3;
    int s  = blockIdx.x % S;
    int nb = (blockIdx.x / S) & 7;
    int mb = blockIdx.x / (S * 8);
    int ntiles = NKT / S;
    int kt0 = s * ntiles;

    const char* Abase = (const char*)(Af + ((size_t)mb * NKT + kt0) * 4096);
    const char* Bbase = (const char*)(Bf + ((size_t)nb * NKT + kt0) * 4096);

    float acc[4][4][4];
    #pragma unroll
    for (int i = 0; i < 4; i++)
        #pragma unroll
        for (int j = 0; j < 4; j++)
            #pragma unroll
            for (int q = 0; q < 4; q++) acc[i][j][q] = 0.f;

    auto cp_tile = [&](int kt, int st) {
        uint32_t dA = smb + st * 2 * FTILE_B + tid * 32;
        uint32_t dB = dA + FTILE_B;
        const char* sA = Abase + (size_t)kt * FTILE_B + tid * 32;
        const char* sB = Bbase + (size_t)kt * FTILE_B + tid * 32;
        cp_async16(dA, sA);
        cp_async16(dA + 16, sA + 16);
        cp_async16(dB, sB);
        cp_async16(dB + 16, sB + 16);
    };

    cp_tile(0, 0);
    CP_COMMIT();
    if (ntiles > 1) cp_tile(1, 1);
    CP_COMMIT();

    uint32_t aOff = (uint32_t)((wr * 4) * 2 * 512) + l * 16;   // + mf*1024 + ks*512
    uint32_t bOff = (uint32_t)(FTILE_B + (wc * 4) * 2 * 256) + l * 8; // + nf*512 + ks*256

    for (int kt = 0; kt < ntiles; kt++) {
        int st = kt % NSTAGE;
        CP_WAIT1();
        __syncthreads();
        if (kt + 2 < ntiles) cp_tile(kt + 2, (kt + 2) % NSTAGE);
        CP_COMMIT();

        uint32_t base = smb + st * 2 * FTILE_B;
        #pragma unroll
        for (int ks = 0; ks < 2; ks++) {
            uint32_t afr[4][4], bfr[4][2];
            #pragma unroll
            for (int mf = 0; mf < 4; mf++) {
                uint32_t addr = base + aOff + mf * 1024 + ks * 512;
                asm volatile("ld.shared.v4.u32 {%0,%1,%2,%3}, [%4];"
                             : "=r"(afr[mf][0]), "=r"(afr[mf][1]), "=r"(afr[mf][2]), "=r"(afr[mf][3])
                             : "r"(addr));
            }
            #pragma unroll
            for (int nf = 0; nf < 4; nf++) {
                uint32_t addr = base + bOff + nf * 512 + ks * 256;
                asm volatile("ld.shared.v2.u32 {%0,%1}, [%2];"
                             : "=r"(bfr[nf][0]), "=r"(bfr[nf][1]) : "r"(addr));
            }
            #pragma unroll
            for (int mf = 0; mf < 4; mf++)
                #pragma unroll
                for (int nf = 0; nf < 4; nf++)
                    mma_f16(acc[mf][nf], afr[mf], bfr[nf]);
        }
        __syncthreads();
    }

    float* crow = Cpart + ((size_t)s * BATCH + mb * 128 + wr * 64) * H1 + nb * 128 + wc * 32;
    #pragma unroll
    for (int mf = 0; mf < 4; mf++) {
        int mm = mf * 16 + (l >> 2);
        #pragma unroll
        for (int nf = 0; nf < 4; nf++) {
            int nn = nf * 8 + (l & 3) * 2;
            *(float2*)(crow + (size_t)mm * H1 + nn) = make_float2(acc[mf][nf][0], acc[mf][nf][1]);
            *(float2*)(crow + (size_t)(mm + 8) * H1 + nn) = make_float2(acc[mf][nf][2], acc[mf][nf][3]);
        }
    }
}

// ---------------- fc1 GEMM: row-major path (verified) ----------------
__global__ void __launch_bounds__(256, 2) gemm_rm_kernel(const __half* __restrict__ Ah,
                                                         const __half* __restrict__ Bw,
                                                         float* __restrict__ Cpart,
                                                         int Ntot, int Ktot, int S) {
    extern __shared__ char smc[];
    uint32_t smb = smem_u32(smc);
    int tid = threadIdx.x;
    int w = tid >> 5, l = tid & 31;
    int wr = w >> 2, wc = w & 3;
    int nbn = Ntot >> 7;
    int s  = blockIdx.x % S;
    int nb = (blockIdx.x / S) % nbn;
    int mb = blockIdx.x / (S * nbn);
    int m0 = mb * 128, n0 = nb * 128;
    int Kper = Ktot / S;
    int k_base = s * Kper;
    int ntiles = Kper >> 5;

    int cr = tid >> 2, cq = tid & 3;

    float acc[4][4][4];
    #pragma unroll
    for (int i = 0; i < 4; i++)
        #pragma unroll
        for (int j = 0; j < 4; j++)
            #pragma unroll
            for (int q = 0; q < 4; q++) acc[i][j][q] = 0.f;

    auto cp_A = [&](int kg, int st) {
        uint32_t base = smb + st * 2 * TBUFH_BYTES;
        #pragma unroll
        for (int it = 0; it < 2; it++) {
            int r = cr + it * 64;
            cp_async16(base + r * SROWB + cq * 16,
                       Ah + (size_t)(m0 + r) * Ktot + kg + cq * 8);
        }
    };
    auto cp_B = [&](int kg, int st) {
        uint32_t base = smb + (st * 2 + 1) * TBUFH_BYTES;
        #pragma unroll
        for (int it = 0; it < 2; it++) {
            int r = cr + it * 64;
            cp_async16(base + r * SROWB + cq * 16,
                       Bw + (size_t)(n0 + r) * Ktot + kg + cq * 8);
        }
    };

    cp_A(k_base, 0);
    cp_B(k_base, 0);
    CP_COMMIT();
    if (ntiles > 1) {
        cp_A(k_base + 32, 1);
        cp_B(k_base + 32, 1);
    }
    CP_COMMIT();

    int mlane = l >> 2, klane = l & 3;
    for (int kt = 0; kt < ntiles; kt++) {
        int st = kt % NSTAGE;
        CP_WAIT1();
        __syncthreads();
        if (kt + 2 < ntiles) {
            int kg2 = k_base + ((kt + 2) << 5);
            int st2 = (kt + 2) % NSTAGE;
            cp_A(kg2, st2);
            cp_B(kg2, st2);
        }
        CP_COMMIT();

        const uint32_t* uA = (const uint32_t*)(smc + st * 2 * TBUFH_BYTES);
        const uint32_t* uB = (const uint32_t*)(smc + (st * 2 + 1) * TBUFH_BYTES);
        #pragma unroll
        for (int ks = 0; ks < 2; ks++) {
            int kw = ks * 8 + klane;
            uint32_t afr[4][4], bfr[4][2];
            #pragma unroll
            for (int mf = 0; mf < 4; mf++) {
                int m = wr * 64 + mf * 16 + mlane;
                afr[mf][0] = uA[m * 20 + kw];
                afr[mf][1] = uA[(m + 8) * 20 + kw];
                afr[mf][2] = uA[m * 20 + kw + 4];
                afr[mf][3] = uA[(m + 8) * 20 + kw + 4];
            }
            #pragma unroll
            for (int nf = 0; nf < 4; nf++) {
                int n = wc * 32 + nf * 8 + mlane;
                bfr[nf][0] = uB[n * 20 + kw];
                bfr[nf][1] = uB[n * 20 + kw + 4];
            }
            #pragma unroll
            for (int mf = 0; mf < 4; mf++)
                #pragma unroll
                for (int nf = 0; nf < 4; nf++)
                    mma_f16(acc[mf][nf], afr[mf], bfr[nf]);
        }
        __syncthreads();
    }

    float* crow = Cpart + ((size_t)s * BATCH + m0 + wr * 64) * Ntot + n0 + wc * 32;
    #pragma unroll
    for (int mf = 0; mf < 4; mf++) {
        int mm = mf * 16 + (l >> 2);
        #pragma unroll
        for (int nf = 0; nf < 4; nf++) {
            int nn = nf * 8 + (l & 3) * 2;
            *(float2*)(crow + (size_t)mm * Ntot + nn) = make_float2(acc[mf][nf][0], acc[mf][nf][1]);
            *(float2*)(crow + (size_t)(mm + 8) * Ntot + nn) = make_float2(acc[mf][nf][2], acc[mf][nf][3]);
        }
    }
}

// ---------------- reductions / final ----------------
__global__ void __launch_bounds__(256) reduce0_kernel(const float* __restrict__ bias) {
    int f = blockIdx.x * 256 + threadIdx.x;   // float4 index, 262144 total
    const float4* p = (const float4*)g_part0;
    float4 b = ((const float4*)bias)[f & 255];
    float4 a0 = p[f], a1 = p[f + 262144], a2 = p[f + 2 * 262144], a3 = p[f + 3 * 262144];
    float rx = fmaxf(a0.x + a1.x + a2.x + a3.x + b.x, 0.f);
    float ry = fmaxf(a0.y + a1.y + a2.y + a3.y + b.y, 0.f);
    float rz = fmaxf(a0.z + a1.z + a2.z + a3.z + b.z, 0.f);
    float rw = fmaxf(a0.w + a1.w + a2.w + a3.w + b.w, 0.f);
    uint2 o;
    o.x = pack_h2(rx, ry);
    o.y = pack_h2(rz, rw);
    ((uint2*)g_h0h)[f] = o;
}

__global__ void __launch_bounds__(256) reduce1_kernel(const float* __restrict__ bias) {
    int f = blockIdx.x * 256 + threadIdx.x;   // float4 index, 131072 total
    const float4* p = (const float4*)g_part1;
    float4 b = ((const float4*)bias)[f & 127];
    float4 a0 = p[f], a1 = p[f + 131072], a2 = p[f + 2 * 131072], a3 = p[f + 3 * 131072];
    float4 o;
    o.x = fmaxf(a0.x + a1.x + a2.x + a3.x + b.x, 0.f);
    o.y = fmaxf(a0.y + a1.y + a2.y + a3.y + b.y, 0.f);
    o.z = fmaxf(a0.z + a1.z + a2.z + a3.z + b.z, 0.f);
    o.w = fmaxf(a0.w + a1.w + a2.w + a3.w + b.w, 0.f);
    ((float4*)g_h1)[f] = o;
}

__global__ void __launch_bounds__(256) fc2_kernel(const float* __restrict__ w,
                                                  const float* __restrict__ bias,
                                                  float* __restrict__ out) {
    int wid = threadIdx.x >> 5, lane = threadIdx.x & 31;
    int row = blockIdx.x * 8 + wid;
    const float4* h = (const float4*)(g_h1 + (size_t)row * H2);
    const float4* wv = (const float4*)w;
    float s = 0.f;
    #pragma unroll
    for (int q = 0; q < 4; q++) {
        float4 a = h[lane + q * 32], b = wv[lane + q * 32];
        s += a.x * b.x + a.y * b.y + a.z * b.z + a.w * b.w;
    }
    #pragma unroll
    for (int o = 16; o; o >>= 1) s += __shfl_xor_sync(0xffffffffu, s, o);
    if (lane == 0) out[row] = 1.0f / (1.0f + expf(-(s + bias[0])));
}

// ---------------- launch ----------------
extern "C" void kernel_launch(void* const* d_in, const int* in_sizes, int n_in,
                              void* d_out, int out_size) {
    const float* x    = (const float*)d_in[0];
    const float* W1   = (const float*)d_in[1];
    const float* W2   = (const float*)d_in[2];
    const float* sw1  = (const float*)d_in[3];
    const float* sw2  = (const float*)d_in[4];
    const float* fc0w = (const float*)d_in[5];
    const float* fc0b = (const float*)d_in[6];
    const float* fc1w = (const float*)d_in[7];
    const float* fc1b = (const float*)d_in[8];
    const float* fc2w = (const float*)d_in[9];
    const float* fc2b = (const float*)d_in[10];
    float* out = (float*)d_out;

    __half* w0f;  cudaGetSymbolAddress((void**)&w0f, g_w0f);
    __half* w1h;  cudaGetSymbolAddress((void**)&w1h, g_w1h);
    __half* feat; cudaGetSymbolAddress((void**)&feat, g_feat);
    __half* h0h;  cudaGetSymbolAddress((void**)&h0h, g_h0h);
    float* part0; cudaGetSymbolAddress((void**)&part0, g_part0);
    float* part1; cudaGetSymbolAddress((void**)&part1, g_part1);

    cudaFuncSetAttribute(gemm_frag_kernel, cudaFuncAttributeMaxDynamicSharedMemorySize, SMEM_FRAG);
    cudaFuncSetAttribute(gemm_rm_kernel, cudaFuncAttributeMaxDynamicSharedMemorySize, SMEM_RM);

    init_pairs_kernel<<<1, 32>>>();
    se_kernel<<<BATCH, 256>>>(x, sw1, sw2);
    tfield_kernel<<<dim3(31, BATCH / 16, 2), 256>>>(x, W1, W2);
    featgen_kernel<<<dim3(2, NKT, 8), 256>>>(x);
    w0frag_kernel<<<dim3(4, NKT, 8), 256>>>(fc0w);
    f2h_kernel<<<(H2 * (H1 / 4) + 255) / 256, 256>>>(fc1w, w1h, H2 * (H1 / 4));
    gemm_frag_kernel<<<8 * 8 * 4, 256, SMEM_FRAG>>>(feat, w0f, part0, 4);
    reduce0_kernel<<<1024, 256>>>(fc0b);
    gemm_rm_kernel<<<8 * 4 * 4, 256, SMEM_RM>>>(h0h, w1h, part1, H2, H1, 4);
    reduce1_kernel<<<512, 256>>>(fc1b);
    fc2_kernel<<<BATCH / 8, 256>>>(fc2w, fc2b, out);
}

// round 10
// speedup vs baseline: 1.2804x; 1.2804x over previous
#include <cuda_runtime.h>
#include <cuda_fp16.h>
#include <cstdint>
#include <cstddef>

#define DI __device__ __forceinline__

#define BATCH 1024
#define NF    32
#define NPAIR 496
#define T_LD  1984
#define X_LD  2048
#define HALFK 31744
#define KTOT  63488
#define H1    1024
#define H2    512

// GEMM tile: BM=128, BN=128, BK=32, 256 threads (8 warps: 2 warp-rows x 4 warp-cols,
// warp tile 64x32). fp16 operands in smem, row stride 40 halves (80B) -> conflict-free
// scalar LDS fragment feed. 3-stage cp.async pipeline, A and B both via cp.async.
#define SROWH 40                 // halves per smem row
#define SROWB 80                 // bytes per smem row
#define TBUFH_BYTES (128*SROWB)  // 10240 bytes per tile buffer
#define NSTAGE 3
#define SMEM_DYN (2*NSTAGE*TBUFH_BYTES) // 61440

__device__ float  g_x2[BATCH*X_LD];
__device__ float  g_T[2*BATCH*T_LD];
__device__ __half g_feat[(size_t)BATCH*KTOT];   // materialized bilinear features (130MB)
__device__ __half g_w0h[(size_t)H1*KTOT];       // fp16 fc0 weights (130MB)
__device__ __half g_w1h[H2*H1];
__device__ float  g_part0[4*BATCH*H1];
__device__ __half g_h0h[BATCH*H1];
__device__ float  g_part1[4*BATCH*H2];
__device__ float  g_h1[BATCH*H2];
__device__ int    g_pi[NPAIR];
__device__ int    g_pj[NPAIR];

DI uint32_t smem_u32(const void* p) {
    uint32_t a;
    asm("{ .reg .u64 t; cvta.to.shared.u64 t, %1; cvt.u32.u64 %0, t; }" : "=r"(a) : "l"(p));
    return a;
}

DI void cp_async16(uint32_t dst, const void* src) {
    asm volatile("cp.async.cg.shared.global [%0], [%1], 16;" :: "r"(dst), "l"(src));
}
#define CP_COMMIT() asm volatile("cp.async.commit_group;" ::: "memory")
#define CP_WAIT1()  asm volatile("cp.async.wait_group 1;" ::: "memory")

DI void mma_f16(float* d, const uint32_t* a, const uint32_t* b) {
    asm volatile(
        "mma.sync.aligned.m16n8k16.row.col.f32.f16.f16.f32 "
        "{%0,%1,%2,%3}, {%4,%5,%6,%7}, {%8,%9}, {%0,%1,%2,%3};"
        : "+f"(d[0]), "+f"(d[1]), "+f"(d[2]), "+f"(d[3])
        : "r"(a[0]), "r"(a[1]), "r"(a[2]), "r"(a[3]), "r"(b[0]), "r"(b[1]));
}

DI uint32_t pack_h2(float a, float b) {
    __half2 h = __floats2half2_rn(a, b);
    return *(uint32_t*)&h;
}

// ---------------- SE block (+pair-table init in the extra block) ----------------
__global__ void __launch_bounds__(256) se_kernel(const float* __restrict__ x,
                                                 const float* __restrict__ w1,
                                                 const float* __restrict__ w2) {
    if (blockIdx.x == BATCH) {
        if (threadIdx.x == 0) {
            int idx = 0;
            for (int i = 0; i < NF - 1; i++)
                for (int j = i + 1; j < NF; j++) { g_pi[idx] = i; g_pj[idx] = j; idx++; }
        }
        return;
    }
    __shared__ float xs[X_LD];
    __shared__ float Zs[NF], A1s[4], A2s[NF];
    int b = blockIdx.x, tid = threadIdx.x;
    const float4* xr = (const float4*)(x + (size_t)b * X_LD);
    float4* xs4 = (float4*)xs;
    xs4[tid] = xr[tid];
    xs4[tid + 256] = xr[tid + 256];
    __syncthreads();
    int wid = tid >> 5, lane = tid & 31;
    #pragma unroll
    for (int ff = 0; ff < 4; ff++) {
        int f = wid * 4 + ff;
        float v = xs[f * 64 + lane] + xs[f * 64 + 32 + lane];
        #pragma unroll
        for (int o = 16; o; o >>= 1) v += __shfl_xor_sync(0xffffffffu, v, o);
        if (lane == 0) Zs[f] = v * (1.0f / 64.0f);
    }
    __syncthreads();
    if (tid < 4) {
        float a = 0.f;
        #pragma unroll
        for (int f = 0; f < NF; f++) a += Zs[f] * w1[tid * NF + f];
        A1s[tid] = fmaxf(a, 0.0f);
    }
    __syncthreads();
    if (tid < NF) {
        float a = 0.f;
        #pragma unroll
        for (int r = 0; r < 4; r++) a += A1s[r] * w2[tid * 4 + r];
        A2s[tid] = 1.0f / (1.0f + expf(-a));
    }
    __syncthreads();
    float4* o4 = (float4*)(g_x2 + (size_t)b * X_LD);
    #pragma unroll
    for (int q = 0; q < 2; q++) {
        int i = tid + q * 256;
        float4 v = xs4[i];
        float sc = A2s[i >> 4];
        v.x *= sc; v.y *= sc; v.z *= sc; v.w *= sc;
        o4[i] = v;
    }
}

// t[v][b][i*64+o] = sum_e feats_v[b,i,e] * W_v[i,o,e]
__global__ void __launch_bounds__(256) tfield_kernel(const float* __restrict__ x,
                                                     const float* __restrict__ W1,
                                                     const float* __restrict__ W2) {
    __shared__ float Ws[64 * 68];
    __shared__ float xs[16 * 68];
    __shared__ float ts[1024];
    int v = blockIdx.z, fi = blockIdx.x, b0 = blockIdx.y * 16;
    int tid = threadIdx.x;
    const float* W = (v ? W2 : W1) + (size_t)fi * 4096;
    for (int idx = tid; idx < 4096; idx += 256)
        Ws[(idx >> 6) * 68 + (idx & 63)] = W[idx];
    const float* xsrc = (v ? g_x2 : x) + (size_t)b0 * X_LD + fi * 64;
    for (int idx = tid; idx < 1024; idx += 256)
        xs[(idx >> 6) * 68 + (idx & 63)] = xsrc[(size_t)(idx >> 6) * X_LD + (idx & 63)];
    __syncthreads();
    int o = tid >> 2, bg = tid & 3;
    float s0 = 0.f, s1 = 0.f, s2 = 0.f, s3 = 0.f;
    const float4* wrow = (const float4*)(Ws + o * 68);
    #pragma unroll
    for (int e4 = 0; e4 < 16; e4++) {
        float4 wv = wrow[e4];
        float4 a0 = *(const float4*)(xs + (bg * 4 + 0) * 68 + e4 * 4);
        float4 a1 = *(const float4*)(xs + (bg * 4 + 1) * 68 + e4 * 4);
        float4 a2 = *(const float4*)(xs + (bg * 4 + 2) * 68 + e4 * 4);
        float4 a3 = *(const float4*)(xs + (bg * 4 + 3) * 68 + e4 * 4);
        s0 += wv.x*a0.x + wv.y*a0.y + wv.z*a0.z + wv.w*a0.w;
        s1 += wv.x*a1.x + wv.y*a1.y + wv.z*a1.z + wv.w*a1.w;
        s2 += wv.x*a2.x + wv.y*a2.y + wv.z*a2.z + wv.w*a2.w;
        s3 += wv.x*a3.x + wv.y*a3.y + wv.z*a3.z + wv.w*a3.w;
    }
    ts[(bg * 4 + 0) * 64 + o] = s0;
    ts[(bg * 4 + 1) * 64 + o] = s1;
    ts[(bg * 4 + 2) * 64 + o] = s2;
    ts[(bg * 4 + 3) * 64 + o] = s3;
    __syncthreads();
    float* trow = g_T + (size_t)v * (BATCH * T_LD);
    for (int idx = tid; idx < 1024; idx += 256)
        trow[(size_t)(b0 + (idx >> 6)) * T_LD + fi * 64 + (idx & 63)] = ts[idx];
}

// ---------------- fused prep: featgen + fc0 weight f2h + fc1 weight f2h ----------------
// blocks [0, 31744): featgen — feat[b, v*HALFK + p*64 + e] = T_v[b,i]*x_v[b,j] (fp16)
// blocks [31744, 95232): f2h of fc0 weights (63488 blocks, 256 float4 each)
// blocks [95232, 95744): f2h of fc1 weights (512 blocks)
#define PREP_FEAT   31744
#define PREP_W0     63488
#define PREP_W1B    512
__global__ void __launch_bounds__(256) prep_kernel(const float* __restrict__ x,
                                                   const float* __restrict__ fc0w,
                                                   const float* __restrict__ fc1w) {
    int blk = blockIdx.x;
    int tid = threadIdx.x;
    if (blk < PREP_FEAT) {
        int p = blk % NPAIR;
        int rest = blk / NPAIR;        // 0..63
        int b0 = (rest & 31) * 32;
        int v = rest >> 5;
        int r = tid >> 3, ec = (tid & 7) * 8;
        int ip = g_pi[p], jp = g_pj[p];
        int b = b0 + r;
        const float* tb = g_T + (size_t)v * (BATCH * T_LD) + (size_t)b * T_LD + ip * 64 + ec;
        const float* xb = (v ? g_x2 : x) + (size_t)b * X_LD + jp * 64 + ec;
        float4 t0 = *(const float4*)tb, t1 = *(const float4*)(tb + 4);
        float4 x0 = *(const float4*)xb, x1 = *(const float4*)(xb + 4);
        uint4 o;
        o.x = pack_h2(t0.x * x0.x, t0.y * x0.y);
        o.y = pack_h2(t0.z * x0.z, t0.w * x0.w);
        o.z = pack_h2(t1.x * x1.x, t1.y * x1.y);
        o.w = pack_h2(t1.z * x1.z, t1.w * x1.w);
        *(uint4*)(g_feat + (size_t)b * KTOT + v * HALFK + p * 64 + ec) = o;
    } else if (blk < PREP_FEAT + PREP_W0) {
        int i = (blk - PREP_FEAT) * 256 + tid;
        float4 v = ((const float4*)fc0w)[i];
        uint2 o;
        o.x = pack_h2(v.x, v.y);
        o.y = pack_h2(v.z, v.w);
        ((uint2*)g_w0h)[i] = o;
    } else {
        int i = (blk - PREP_FEAT - PREP_W0) * 256 + tid;
        float4 v = ((const float4*)fc1w)[i];
        uint2 o;
        o.x = pack_h2(v.x, v.y);
        o.y = pack_h2(v.z, v.w);
        ((uint2*)g_w1h)[i] = o;
    }
}

// ---------------- mma.sync fp16 GEMM (pure cp.async, 3-stage) ----------------
// C[m,n] = sum_k A[m,k] * W[n,k]; A, W fp16 row-major with row stride Ktot.
__global__ void __launch_bounds__(256, 2) gemm_kernel(const __half* __restrict__ Ah,
                                                      const __half* __restrict__ Bw,
                                                      float* __restrict__ Cpart,
                                                      int Ntot, int Ktot, int S) {
    extern __shared__ char smc[];
    uint32_t smb = smem_u32(smc);
    int tid = threadIdx.x;
    int w = tid >> 5, l = tid & 31;
    int wr = w >> 2, wc = w & 3;
    int nbn = Ntot >> 7;
    int s  = blockIdx.x % S;
    int nb = (blockIdx.x / S) % nbn;
    int mb = blockIdx.x / (S * nbn);
    int m0 = mb * 128, n0 = nb * 128;
    int Kper = Ktot / S;
    int k_base = s * Kper;
    int ntiles = Kper >> 5;

    int cr = tid >> 2, cq = tid & 3;         // cp.async: rows cr,cr+64; 16B chunk cq

    float acc[4][4][4];
    #pragma unroll
    for (int i = 0; i < 4; i++)
        #pragma unroll
        for (int j = 0; j < 4; j++)
            #pragma unroll
            for (int q = 0; q < 4; q++) acc[i][j][q] = 0.f;

    auto cp_A = [&](int kg, int st) {
        uint32_t base = smb + st * 2 * TBUFH_BYTES;
        #pragma unroll
        for (int it = 0; it < 2; it++) {
            int r = cr + it * 64;
            cp_async16(base + r * SROWB + cq * 16,
                       Ah + (size_t)(m0 + r) * Ktot + kg + cq * 8);
        }
    };
    auto cp_B = [&](int kg, int st) {
        uint32_t base = smb + (st * 2 + 1) * TBUFH_BYTES;
        #pragma unroll
        for (int it = 0; it < 2; it++) {
            int r = cr + it * 64;
            cp_async16(base + r * SROWB + cq * 16,
                       Bw + (size_t)(n0 + r) * Ktot + kg + cq * 8);
        }
    };

    cp_A(k_base, 0);
    cp_B(k_base, 0);
    CP_COMMIT();
    if (ntiles > 1) {
        cp_A(k_base + 32, 1);
        cp_B(k_base + 32, 1);
    }
    CP_COMMIT();

    int mlane = l >> 2, klane = l & 3;
    for (int kt = 0; kt < ntiles; kt++) {
        int st = kt % NSTAGE;
        CP_WAIT1();
        __syncthreads();
        if (kt + 2 < ntiles) {
            int kg2 = k_base + ((kt + 2) << 5);
            int st2 = (kt + 2) % NSTAGE;
            cp_A(kg2, st2);
            cp_B(kg2, st2);
        }
        CP_COMMIT();

        const uint32_t* uA = (const uint32_t*)(smc + st * 2 * TBUFH_BYTES);
        const uint32_t* uB = (const uint32_t*)(smc + (st * 2 + 1) * TBUFH_BYTES);
        #pragma unroll
        for (int ks = 0; ks < 2; ks++) {
            int kw = ks * 8 + klane;
            uint32_t afr[4][4], bfr[4][2];
            #pragma unroll
            for (int mf = 0; mf < 4; mf++) {
                int m = wr * 64 + mf * 16 + mlane;
                afr[mf][0] = uA[m * 20 + kw];
                afr[mf][1] = uA[(m + 8) * 20 + kw];
                afr[mf][2] = uA[m * 20 + kw + 4];
                afr[mf][3] = uA[(m + 8) * 20 + kw + 4];
            }
            #pragma unroll
            for (int nf = 0; nf < 4; nf++) {
                int n = wc * 32 + nf * 8 + mlane;
                bfr[nf][0] = uB[n * 20 + kw];
                bfr[nf][1] = uB[n * 20 + kw + 4];
            }
            #pragma unroll
            for (int mf = 0; mf < 4; mf++)
                #pragma unroll
                for (int nf = 0; nf < 4; nf++)
                    mma_f16(acc[mf][nf], afr[mf], bfr[nf]);
        }
        __syncthreads();
    }

    float* crow = Cpart + ((size_t)s * BATCH + m0 + wr * 64) * Ntot + n0 + wc * 32;
    #pragma unroll
    for (int mf = 0; mf < 4; mf++) {
        int mm = mf * 16 + (l >> 2);
        #pragma unroll
        for (int nf = 0; nf < 4; nf++) {
            int nn = nf * 8 + (l & 3) * 2;
            *(float2*)(crow + (size_t)mm * Ntot + nn) = make_float2(acc[mf][nf][0], acc[mf][nf][1]);
            *(float2*)(crow + (size_t)(mm + 8) * Ntot + nn) = make_float2(acc[mf][nf][2], acc[mf][nf][3]);
        }
    }
}

// ---------------- reductions / final ----------------
__global__ void __launch_bounds__(256) reduce0_kernel(const float* __restrict__ bias) {
    int f = blockIdx.x * 256 + threadIdx.x;   // float4 index, 262144 total
    const float4* p = (const float4*)g_part0;
    float4 b = ((const float4*)bias)[f & 255];
    float4 a0 = p[f], a1 = p[f + 262144], a2 = p[f + 2 * 262144], a3 = p[f + 3 * 262144];
    float rx = fmaxf(a0.x + a1.x + a2.x + a3.x + b.x, 0.f);
    float ry = fmaxf(a0.y + a1.y + a2.y + a3.y + b.y, 0.f);
    float rz = fmaxf(a0.z + a1.z + a2.z + a3.z + b.z, 0.f);
    float rw = fmaxf(a0.w + a1.w + a2.w + a3.w + b.w, 0.f);
    uint2 o;
    o.x = pack_h2(rx, ry);
    o.y = pack_h2(rz, rw);
    ((uint2*)g_h0h)[f] = o;
}

__global__ void __launch_bounds__(256) reduce1_kernel(const float* __restrict__ bias) {
    int f = blockIdx.x * 256 + threadIdx.x;   // float4 index, 131072 total
    const float4* p = (const float4*)g_part1;
    float4 b = ((const float4*)bias)[f & 127];
    float4 a0 = p[f], a1 = p[f + 131072], a2 = p[f + 2 * 131072], a3 = p[f + 3 * 131072];
    float4 o;
    o.x = fmaxf(a0.x + a1.x + a2.x + a3.x + b.x, 0.f);
    o.y = fmaxf(a0.y + a1.y + a2.y + a3.y + b.y, 0.f);
    o.z = fmaxf(a0.z + a1.z + a2.z + a3.z + b.z, 0.f);
    o.w = fmaxf(a0.w + a1.w + a2.w + a3.w + b.w, 0.f);
    ((float4*)g_h1)[f] = o;
}

__global__ void __launch_bounds__(256) fc2_kernel(const float* __restrict__ w,
                                                  const float* __restrict__ bias,
                                                  float* __restrict__ out) {
    int wid = threadIdx.x >> 5, lane = threadIdx.x & 31;
    int row = blockIdx.x * 8 + wid;
    const float4* h = (const float4*)(g_h1 + (size_t)row * H2);
    const float4* wv = (const float4*)w;
    float s = 0.f;
    #pragma unroll
    for (int q = 0; q < 4; q++) {
        float4 a = h[lane + q * 32], b = wv[lane + q * 32];
        s += a.x * b.x + a.y * b.y + a.z * b.z + a.w * b.w;
    }
    #pragma unroll
    for (int o = 16; o; o >>= 1) s += __shfl_xor_sync(0xffffffffu, s, o);
    if (lane == 0) out[row] = 1.0f / (1.0f + expf(-(s + bias[0])));
}

// ---------------- launch ----------------
extern "C" void kernel_launch(void* const* d_in, const int* in_sizes, int n_in,
                              void* d_out, int out_size) {
    const float* x    = (const float*)d_in[0];
    const float* W1   = (const float*)d_in[1];
    const float* W2   = (const float*)d_in[2];
    const float* sw1  = (const float*)d_in[3];
    const float* sw2  = (const float*)d_in[4];
    const float* fc0w = (const float*)d_in[5];
    const float* fc0b = (const float*)d_in[6];
    const float* fc1w = (const float*)d_in[7];
    const float* fc1b = (const float*)d_in[8];
    const float* fc2w = (const float*)d_in[9];
    const float* fc2b = (const float*)d_in[10];
    float* out = (float*)d_out;

    __half* w0h;  cudaGetSymbolAddress((void**)&w0h, g_w0h);
    __half* w1h;  cudaGetSymbolAddress((void**)&w1h, g_w1h);
    __half* feat; cudaGetSymbolAddress((void**)&feat, g_feat);
    __half* h0h;  cudaGetSymbolAddress((void**)&h0h, g_h0h);
    float* part0; cudaGetSymbolAddress((void**)&part0, g_part0);
    float* part1; cudaGetSymbolAddress((void**)&part1, g_part1);

    cudaFuncSetAttribute(gemm_kernel, cudaFuncAttributeMaxDynamicSharedMemorySize, SMEM_DYN);

    se_kernel<<<BATCH + 1, 256>>>(x, sw1, sw2);                      // #1 (+pair init)
    tfield_kernel<<<dim3(31, BATCH / 16, 2), 256>>>(x, W1, W2);      // #2
    prep_kernel<<<PREP_FEAT + PREP_W0 + PREP_W1B, 256>>>(x, fc0w, fc1w); // #3
    gemm_kernel<<<8 * 8 * 4, 256, SMEM_DYN>>>(feat, w0h, part0, H1, KTOT, 4); // #4 <- profiled
    reduce0_kernel<<<1024, 256>>>(fc0b);
    gemm_kernel<<<8 * 4 * 4, 256, SMEM_DYN>>>(h0h, w1h, part1, H2, H1, 4);
    reduce1_kernel<<<512, 256>>>(fc1b);
    fc2_kernel<<<BATCH / 8, 256>>>(fc2w, fc2b, out);
}

// round 11
// speedup vs baseline: 1.4106x; 1.1017x over previous
#include <cuda_runtime.h>
#include <cuda_fp16.h>
#include <cstdint>
#include <cstddef>

#define DI __device__ __forceinline__

#define BATCH 1024
#define NF    32
#define NPAIR 496
#define T_LD  1984
#define X_LD  2048
#define HALFK 31744
#define KTOT  63488
#define H1    1024
#define H2    512
#define S0    16                 // fc0 split-K
#define S1    8                  // fc1 split-K

// GEMM tile: BM=128, BN=128, BK=32, 256 threads (8 warps: 2 warp-rows x 4 warp-cols,
// warp tile 64x32). fp16 operands in smem, row stride 40 halves (80B) -> conflict-free
// scalar LDS fragment feed. 3-stage cp.async pipeline, A and B both via cp.async.
#define SROWH 40
#define SROWB 80
#define TBUFH_BYTES (128*SROWB)  // 10240
#define NSTAGE 3
#define SMEM_DYN (2*NSTAGE*TBUFH_BYTES) // 61440

__device__ float  g_x2[BATCH*X_LD];
__device__ float  g_T[2*BATCH*T_LD];
__device__ __half g_feat[(size_t)BATCH*KTOT];   // materialized bilinear features (130MB)
__device__ __half g_w0h[(size_t)H1*KTOT];       // fp16 fc0 weights (130MB)
__device__ __half g_w1h[H2*H1];
__device__ float  g_part0[(size_t)S0*BATCH*H1]; // 64MB
__device__ __half g_h0h[BATCH*H1];
__device__ float  g_part1[(size_t)S1*BATCH*H2]; // 16MB
__device__ float  g_h1[BATCH*H2];
__device__ int    g_pi[NPAIR];
__device__ int    g_pj[NPAIR];

DI uint32_t smem_u32(const void* p) {
    uint32_t a;
    asm("{ .reg .u64 t; cvta.to.shared.u64 t, %1; cvt.u32.u64 %0, t; }" : "=r"(a) : "l"(p));
    return a;
}

DI void cp_async16(uint32_t dst, const void* src) {
    asm volatile("cp.async.cg.shared.global [%0], [%1], 16;" :: "r"(dst), "l"(src));
}
#define CP_COMMIT() asm volatile("cp.async.commit_group;" ::: "memory")
#define CP_WAIT1()  asm volatile("cp.async.wait_group 1;" ::: "memory")

DI void mma_f16(float* d, const uint32_t* a, const uint32_t* b) {
    asm volatile(
        "mma.sync.aligned.m16n8k16.row.col.f32.f16.f16.f32 "
        "{%0,%1,%2,%3}, {%4,%5,%6,%7}, {%8,%9}, {%0,%1,%2,%3};"
        : "+f"(d[0]), "+f"(d[1]), "+f"(d[2]), "+f"(d[3])
        : "r"(a[0]), "r"(a[1]), "r"(a[2]), "r"(a[3]), "r"(b[0]), "r"(b[1]));
}

DI uint32_t pack_h2(float a, float b) {
    __half2 h = __floats2half2_rn(a, b);
    return *(uint32_t*)&h;
}

// ---------------- SE block (+pair-table init in the extra block) ----------------
__global__ void __launch_bounds__(256) se_kernel(const float* __restrict__ x,
                                                 const float* __restrict__ w1,
                                                 const float* __restrict__ w2) {
    if (blockIdx.x == BATCH) {
        if (threadIdx.x == 0) {
            int idx = 0;
            for (int i = 0; i < NF - 1; i++)
                for (int j = i + 1; j < NF; j++) { g_pi[idx] = i; g_pj[idx] = j; idx++; }
        }
        return;
    }
    __shared__ float xs[X_LD];
    __shared__ float Zs[NF], A1s[4], A2s[NF];
    int b = blockIdx.x, tid = threadIdx.x;
    const float4* xr = (const float4*)(x + (size_t)b * X_LD);
    float4* xs4 = (float4*)xs;
    xs4[tid] = xr[tid];
    xs4[tid + 256] = xr[tid + 256];
    __syncthreads();
    int wid = tid >> 5, lane = tid & 31;
    #pragma unroll
    for (int ff = 0; ff < 4; ff++) {
        int f = wid * 4 + ff;
        float v = xs[f * 64 + lane] + xs[f * 64 + 32 + lane];
        #pragma unroll
        for (int o = 16; o; o >>= 1) v += __shfl_xor_sync(0xffffffffu, v, o);
        if (lane == 0) Zs[f] = v * (1.0f / 64.0f);
    }
    __syncthreads();
    if (tid < 4) {
        float a = 0.f;
        #pragma unroll
        for (int f = 0; f < NF; f++) a += Zs[f] * w1[tid * NF + f];
        A1s[tid] = fmaxf(a, 0.0f);
    }
    __syncthreads();
    if (tid < NF) {
        float a = 0.f;
        #pragma unroll
        for (int r = 0; r < 4; r++) a += A1s[r] * w2[tid * 4 + r];
        A2s[tid] = 1.0f / (1.0f + expf(-a));
    }
    __syncthreads();
    float4* o4 = (float4*)(g_x2 + (size_t)b * X_LD);
    #pragma unroll
    for (int q = 0; q < 2; q++) {
        int i = tid + q * 256;
        float4 v = xs4[i];
        float sc = A2s[i >> 4];
        v.x *= sc; v.y *= sc; v.z *= sc; v.w *= sc;
        o4[i] = v;
    }
}

// t[v][b][i*64+o] = sum_e feats_v[b,i,e] * W_v[i,o,e]
__global__ void __launch_bounds__(256) tfield_kernel(const float* __restrict__ x,
                                                     const float* __restrict__ W1,
                                                     const float* __restrict__ W2) {
    __shared__ float Ws[64 * 68];
    __shared__ float xs[16 * 68];
    __shared__ float ts[1024];
    int v = blockIdx.z, fi = blockIdx.x, b0 = blockIdx.y * 16;
    int tid = threadIdx.x;
    const float* W = (v ? W2 : W1) + (size_t)fi * 4096;
    for (int idx = tid; idx < 4096; idx += 256)
        Ws[(idx >> 6) * 68 + (idx & 63)] = W[idx];
    const float* xsrc = (v ? g_x2 : x) + (size_t)b0 * X_LD + fi * 64;
    for (int idx = tid; idx < 1024; idx += 256)
        xs[(idx >> 6) * 68 + (idx & 63)] = xsrc[(size_t)(idx >> 6) * X_LD + (idx & 63)];
    __syncthreads();
    int o = tid >> 2, bg = tid & 3;
    float s0 = 0.f, s1 = 0.f, s2 = 0.f, s3 = 0.f;
    const float4* wrow = (const float4*)(Ws + o * 68);
    #pragma unroll
    for (int e4 = 0; e4 < 16; e4++) {
        float4 wv = wrow[e4];
        float4 a0 = *(const float4*)(xs + (bg * 4 + 0) * 68 + e4 * 4);
        float4 a1 = *(const float4*)(xs + (bg * 4 + 1) * 68 + e4 * 4);
        float4 a2 = *(const float4*)(xs + (bg * 4 + 2) * 68 + e4 * 4);
        float4 a3 = *(const float4*)(xs + (bg * 4 + 3) * 68 + e4 * 4);
        s0 += wv.x*a0.x + wv.y*a0.y + wv.z*a0.z + wv.w*a0.w;
        s1 += wv.x*a1.x + wv.y*a1.y + wv.z*a1.z + wv.w*a1.w;
        s2 += wv.x*a2.x + wv.y*a2.y + wv.z*a2.z + wv.w*a2.w;
        s3 += wv.x*a3.x + wv.y*a3.y + wv.z*a3.z + wv.w*a3.w;
    }
    ts[(bg * 4 + 0) * 64 + o] = s0;
    ts[(bg * 4 + 1) * 64 + o] = s1;
    ts[(bg * 4 + 2) * 64 + o] = s2;
    ts[(bg * 4 + 3) * 64 + o] = s3;
    __syncthreads();
    float* trow = g_T + (size_t)v * (BATCH * T_LD);
    for (int idx = tid; idx < 1024; idx += 256)
        trow[(size_t)(b0 + (idx >> 6)) * T_LD + fi * 64 + (idx & 63)] = ts[idx];
}

// ---------------- fused prep: featgen + fc0 weight f2h + fc1 weight f2h ----------------
#define PREP_FEAT   31744
#define PREP_W0     63488
#define PREP_W1B    512
__global__ void __launch_bounds__(256) prep_kernel(const float* __restrict__ x,
                                                   const float* __restrict__ fc0w,
                                                   const float* __restrict__ fc1w) {
    int blk = blockIdx.x;
    int tid = threadIdx.x;
    if (blk < PREP_FEAT) {
        int p = blk % NPAIR;
        int rest = blk / NPAIR;        // 0..63
        int b0 = (rest & 31) * 32;
        int v = rest >> 5;
        int r = tid >> 3, ec = (tid & 7) * 8;
        int ip = g_pi[p], jp = g_pj[p];
        int b = b0 + r;
        const float* tb = g_T + (size_t)v * (BATCH * T_LD) + (size_t)b * T_LD + ip * 64 + ec;
        const float* xb = (v ? g_x2 : x) + (size_t)b * X_LD + jp * 64 + ec;
        float4 t0 = *(const float4*)tb, t1 = *(const float4*)(tb + 4);
        float4 x0 = *(const float4*)xb, x1 = *(const float4*)(xb + 4);
        uint4 o;
        o.x = pack_h2(t0.x * x0.x, t0.y * x0.y);
        o.y = pack_h2(t0.z * x0.z, t0.w * x0.w);
        o.z = pack_h2(t1.x * x1.x, t1.y * x1.y);
        o.w = pack_h2(t1.z * x1.z, t1.w * x1.w);
        *(uint4*)(g_feat + (size_t)b * KTOT + v * HALFK + p * 64 + ec) = o;
    } else if (blk < PREP_FEAT + PREP_W0) {
        int i = (blk - PREP_FEAT) * 256 + tid;
        float4 v = ((const float4*)fc0w)[i];
        uint2 o;
        o.x = pack_h2(v.x, v.y);
        o.y = pack_h2(v.z, v.w);
        ((uint2*)g_w0h)[i] = o;
    } else {
        int i = (blk - PREP_FEAT - PREP_W0) * 256 + tid;
        float4 v = ((const float4*)fc1w)[i];
        uint2 o;
        o.x = pack_h2(v.x, v.y);
        o.y = pack_h2(v.z, v.w);
        ((uint2*)g_w1h)[i] = o;
    }
}

// ---------------- mma.sync fp16 GEMM (pure cp.async, 3-stage) ----------------
// C[m,n] = sum_k A[m,k] * W[n,k]; A, W fp16 row-major with row stride Ktot.
// CTA decode: mb fastest, then nb, then s -> one s-group's CTAs co-resident in L2.
__global__ void __launch_bounds__(256, 2) gemm_kernel(const __half* __restrict__ Ah,
                                                      const __half* __restrict__ Bw,
                                                      float* __restrict__ Cpart,
                                                      int Ntot, int Ktot, int S) {
    extern __shared__ char smc[];
    uint32_t smb = smem_u32(smc);
    int tid = threadIdx.x;
    int w = tid >> 5, l = tid & 31;
    int wr = w >> 2, wc = w & 3;
    int nbn = Ntot >> 7;
    int mb = blockIdx.x % 8;
    int nb = (blockIdx.x / 8) % nbn;
    int s  = blockIdx.x / (8 * nbn);
    int m0 = mb * 128, n0 = nb * 128;
    int Kper = Ktot / S;
    int k_base = s * Kper;
    int ntiles = Kper >> 5;

    int cr = tid >> 2, cq = tid & 3;         // cp.async: rows cr,cr+64; 16B chunk cq

    float acc[4][4][4];
    #pragma unroll
    for (int i = 0; i < 4; i++)
        #pragma unroll
        for (int j = 0; j < 4; j++)
            #pragma unroll
            for (int q = 0; q < 4; q++) acc[i][j][q] = 0.f;

    auto cp_A = [&](int kg, int st) {
        uint32_t base = smb + st * 2 * TBUFH_BYTES;
        #pragma unroll
        for (int it = 0; it < 2; it++) {
            int r = cr + it * 64;
            cp_async16(base + r * SROWB + cq * 16,
                       Ah + (size_t)(m0 + r) * Ktot + kg + cq * 8);
        }
    };
    auto cp_B = [&](int kg, int st) {
        uint32_t base = smb + (st * 2 + 1) * TBUFH_BYTES;
        #pragma unroll
        for (int it = 0; it < 2; it++) {
            int r = cr + it * 64;
            cp_async16(base + r * SROWB + cq * 16,
                       Bw + (size_t)(n0 + r) * Ktot + kg + cq * 8);
        }
    };

    cp_A(k_base, 0);
    cp_B(k_base, 0);
    CP_COMMIT();
    if (ntiles > 1) {
        cp_A(k_base + 32, 1);
        cp_B(k_base + 32, 1);
    }
    CP_COMMIT();

    int mlane = l >> 2, klane = l & 3;
    for (int kt = 0; kt < ntiles; kt++) {
        int st = kt % NSTAGE;
        CP_WAIT1();
        __syncthreads();
        if (kt + 2 < ntiles) {
            int kg2 = k_base + ((kt + 2) << 5);
            int st2 = (kt + 2) % NSTAGE;
            cp_A(kg2, st2);
            cp_B(kg2, st2);
        }
        CP_COMMIT();

        const uint32_t* uA = (const uint32_t*)(smc + st * 2 * TBUFH_BYTES);
        const uint32_t* uB = (const uint32_t*)(smc + (st * 2 + 1) * TBUFH_BYTES);
        #pragma unroll
        for (int ks = 0; ks < 2; ks++) {
            int kw = ks * 8 + klane;
            uint32_t afr[4][4], bfr[4][2];
            #pragma unroll
            for (int mf = 0; mf < 4; mf++) {
                int m = wr * 64 + mf * 16 + mlane;
                afr[mf][0] = uA[m * 20 + kw];
                afr[mf][1] = uA[(m + 8) * 20 + kw];
                afr[mf][2] = uA[m * 20 + kw + 4];
                afr[mf][3] = uA[(m + 8) * 20 + kw + 4];
            }
            #pragma unroll
            for (int nf = 0; nf < 4; nf++) {
                int n = wc * 32 + nf * 8 + mlane;
                bfr[nf][0] = uB[n * 20 + kw];
                bfr[nf][1] = uB[n * 20 + kw + 4];
            }
            #pragma unroll
            for (int mf = 0; mf < 4; mf++)
                #pragma unroll
                for (int nf = 0; nf < 4; nf++)
                    mma_f16(acc[mf][nf], afr[mf], bfr[nf]);
        }
        __syncthreads();
    }

    float* crow = Cpart + ((size_t)s * BATCH + m0 + wr * 64) * Ntot + n0 + wc * 32;
    #pragma unroll
    for (int mf = 0; mf < 4; mf++) {
        int mm = mf * 16 + (l >> 2);
        #pragma unroll
        for (int nf = 0; nf < 4; nf++) {
            int nn = nf * 8 + (l & 3) * 2;
            *(float2*)(crow + (size_t)mm * Ntot + nn) = make_float2(acc[mf][nf][0], acc[mf][nf][1]);
            *(float2*)(crow + (size_t)(mm + 8) * Ntot + nn) = make_float2(acc[mf][nf][2], acc[mf][nf][3]);
        }
    }
}

// ---------------- reductions / final ----------------
__global__ void __launch_bounds__(256) reduce0_kernel(const float* __restrict__ bias) {
    int f = blockIdx.x * 256 + threadIdx.x;   // float4 index, 262144 total
    const float4* p = (const float4*)g_part0;
    float4 b = ((const float4*)bias)[f & 255];
    float sx = b.x, sy = b.y, sz = b.z, sw = b.w;
    #pragma unroll
    for (int i = 0; i < S0; i++) {
        float4 a = p[f + (size_t)i * 262144];
        sx += a.x; sy += a.y; sz += a.z; sw += a.w;
    }
    uint2 o;
    o.x = pack_h2(fmaxf(sx, 0.f), fmaxf(sy, 0.f));
    o.y = pack_h2(fmaxf(sz, 0.f), fmaxf(sw, 0.f));
    ((uint2*)g_h0h)[f] = o;
}

__global__ void __launch_bounds__(256) reduce1_kernel(const float* __restrict__ bias) {
    int f = blockIdx.x * 256 + threadIdx.x;   // float4 index, 131072 total
    const float4* p = (const float4*)g_part1;
    float4 b = ((const float4*)bias)[f & 127];
    float sx = b.x, sy = b.y, sz = b.z, sw = b.w;
    #pragma unroll
    for (int i = 0; i < S1; i++) {
        float4 a = p[f + (size_t)i * 131072];
        sx += a.x; sy += a.y; sz += a.z; sw += a.w;
    }
    float4 o;
    o.x = fmaxf(sx, 0.f); o.y = fmaxf(sy, 0.f);
    o.z = fmaxf(sz, 0.f); o.w = fmaxf(sw, 0.f);
    ((float4*)g_h1)[f] = o;
}

__global__ void __launch_bounds__(256) fc2_kernel(const float* __restrict__ w,
                                                  const float* __restrict__ bias,
                                                  float* __restrict__ out) {
    int wid = threadIdx.x >> 5, lane = threadIdx.x & 31;
    int row = blockIdx.x * 8 + wid;
    const float4* h = (const float4*)(g_h1 + (size_t)row * H2);
    const float4* wv = (const float4*)w;
    float s = 0.f;
    #pragma unroll
    for (int q = 0; q < 4; q++) {
        float4 a = h[lane + q * 32], b = wv[lane + q * 32];
        s += a.x * b.x + a.y * b.y + a.z * b.z + a.w * b.w;
    }
    #pragma unroll
    for (int o = 16; o; o >>= 1) s += __shfl_xor_sync(0xffffffffu, s, o);
    if (lane == 0) out[row] = 1.0f / (1.0f + expf(-(s + bias[0])));
}

// ---------------- launch ----------------
extern "C" void kernel_launch(void* const* d_in, const int* in_sizes, int n_in,
                              void* d_out, int out_size) {
    const float* x    = (const float*)d_in[0];
    const float* W1   = (const float*)d_in[1];
    const float* W2   = (const float*)d_in[2];
    const float* sw1  = (const float*)d_in[3];
    const float* sw2  = (const float*)d_in[4];
    const float* fc0w = (const float*)d_in[5];
    const float* fc0b = (const float*)d_in[6];
    const float* fc1w = (const float*)d_in[7];
    const float* fc1b = (const float*)d_in[8];
    const float* fc2w = (const float*)d_in[9];
    const float* fc2b = (const float*)d_in[10];
    float* out = (float*)d_out;

    __half* w0h;  cudaGetSymbolAddress((void**)&w0h, g_w0h);
    __half* w1h;  cudaGetSymbolAddress((void**)&w1h, g_w1h);
    __half* feat; cudaGetSymbolAddress((void**)&feat, g_feat);
    __half* h0h;  cudaGetSymbolAddress((void**)&h0h, g_h0h);
    float* part0; cudaGetSymbolAddress((void**)&part0, g_part0);
    float* part1; cudaGetSymbolAddress((void**)&part1, g_part1);

    cudaFuncSetAttribute(gemm_kernel, cudaFuncAttributeMaxDynamicSharedMemorySize, SMEM_DYN);

    se_kernel<<<BATCH + 1, 256>>>(x, sw1, sw2);                      // #1 (+pair init)
    tfield_kernel<<<dim3(31, BATCH / 16, 2), 256>>>(x, W1, W2);      // #2
    prep_kernel<<<PREP_FEAT + PREP_W0 + PREP_W1B, 256>>>(x, fc0w, fc1w); // #3
    gemm_kernel<<<8 * 8 * S0, 256, SMEM_DYN>>>(feat, w0h, part0, H1, KTOT, S0); // #4 <- profiled
    reduce0_kernel<<<1024, 256>>>(fc0b);
    gemm_kernel<<<8 * 4 * S1, 256, SMEM_DYN>>>(h0h, w1h, part1, H2, H1, S1);
    reduce1_kernel<<<512, 256>>>(fc1b);
    fc2_kernel<<<BATCH / 8, 256>>>(fc2w, fc2b, out);
}

// round 12
// speedup vs baseline: 1.4702x; 1.0423x over previous
#include <cuda_runtime.h>
#include <cuda_fp16.h>
#include <cstdint>
#include <cstddef>

#define DI __device__ __forceinline__

#define BATCH 1024
#define NF    32
#define NPAIR 496
#define T_LD  1984
#define X_LD  2048
#define HALFK 31744
#define KTOT  63488
#define H1    1024
#define H2    512
#define S0    16                 // fc0 split-K
#define S1    8                  // fc1 split-K

// GEMM tile: BM=128, BN=128, BK=64, 256 threads (8 warps: 2 warp-rows x 4 warp-cols,
// warp tile 64x32). fp16 operands in smem, row stride 72 halves (144B) -> conflict-free
// scalar LDS feed (bank = 4*mlane + klane mod 32, all distinct). 2-stage cp.async pipeline.
#define SROWH 72
#define SROWB 144
#define TBUFH_BYTES (128*SROWB)  // 18432
#define NSTAGE 2
#define SMEM_DYN (2*NSTAGE*TBUFH_BYTES) // 73728

__device__ float  g_x2[BATCH*X_LD];
__device__ float  g_T[2*BATCH*T_LD];
__device__ __half g_feat[(size_t)BATCH*KTOT];   // materialized bilinear features (130MB)
__device__ __half g_w0h[(size_t)H1*KTOT];       // fp16 fc0 weights (130MB)
__device__ __half g_w1h[H2*H1];
__device__ float  g_part0[(size_t)S0*BATCH*H1]; // 64MB
__device__ __half g_h0h[BATCH*H1];
__device__ float  g_part1[(size_t)S1*BATCH*H2]; // 16MB
__device__ float  g_h1[BATCH*H2];
__device__ int    g_pi[NPAIR];
__device__ int    g_pj[NPAIR];

DI uint32_t smem_u32(const void* p) {
    uint32_t a;
    asm("{ .reg .u64 t; cvta.to.shared.u64 t, %1; cvt.u32.u64 %0, t; }" : "=r"(a) : "l"(p));
    return a;
}

DI void cp_async16(uint32_t dst, const void* src) {
    asm volatile("cp.async.cg.shared.global [%0], [%1], 16;" :: "r"(dst), "l"(src));
}
#define CP_COMMIT() asm volatile("cp.async.commit_group;" ::: "memory")
#define CP_WAIT0()  asm volatile("cp.async.wait_group 0;" ::: "memory")

DI void mma_f16(float* d, const uint32_t* a, const uint32_t* b) {
    asm volatile(
        "mma.sync.aligned.m16n8k16.row.col.f32.f16.f16.f32 "
        "{%0,%1,%2,%3}, {%4,%5,%6,%7}, {%8,%9}, {%0,%1,%2,%3};"
        : "+f"(d[0]), "+f"(d[1]), "+f"(d[2]), "+f"(d[3])
        : "r"(a[0]), "r"(a[1]), "r"(a[2]), "r"(a[3]), "r"(b[0]), "r"(b[1]));
}

DI uint32_t pack_h2(float a, float b) {
    __half2 h = __floats2half2_rn(a, b);
    return *(uint32_t*)&h;
}

// ---------------- SE block (+pair-table init in the extra block) ----------------
__global__ void __launch_bounds__(256) se_kernel(const float* __restrict__ x,
                                                 const float* __restrict__ w1,
                                                 const float* __restrict__ w2) {
    if (blockIdx.x == BATCH) {
        if (threadIdx.x == 0) {
            int idx = 0;
            for (int i = 0; i < NF - 1; i++)
                for (int j = i + 1; j < NF; j++) { g_pi[idx] = i; g_pj[idx] = j; idx++; }
        }
        return;
    }
    __shared__ float xs[X_LD];
    __shared__ float Zs[NF], A1s[4], A2s[NF];
    int b = blockIdx.x, tid = threadIdx.x;
    const float4* xr = (const float4*)(x + (size_t)b * X_LD);
    float4* xs4 = (float4*)xs;
    xs4[tid] = xr[tid];
    xs4[tid + 256] = xr[tid + 256];
    __syncthreads();
    int wid = tid >> 5, lane = tid & 31;
    #pragma unroll
    for (int ff = 0; ff < 4; ff++) {
        int f = wid * 4 + ff;
        float v = xs[f * 64 + lane] + xs[f * 64 + 32 + lane];
        #pragma unroll
        for (int o = 16; o; o >>= 1) v += __shfl_xor_sync(0xffffffffu, v, o);
        if (lane == 0) Zs[f] = v * (1.0f / 64.0f);
    }
    __syncthreads();
    if (tid < 4) {
        float a = 0.f;
        #pragma unroll
        for (int f = 0; f < NF; f++) a += Zs[f] * w1[tid * NF + f];
        A1s[tid] = fmaxf(a, 0.0f);
    }
    __syncthreads();
    if (tid < NF) {
        float a = 0.f;
        #pragma unroll
        for (int r = 0; r < 4; r++) a += A1s[r] * w2[tid * 4 + r];
        A2s[tid] = 1.0f / (1.0f + expf(-a));
    }
    __syncthreads();
    float4* o4 = (float4*)(g_x2 + (size_t)b * X_LD);
    #pragma unroll
    for (int q = 0; q < 2; q++) {
        int i = tid + q * 256;
        float4 v = xs4[i];
        float sc = A2s[i >> 4];
        v.x *= sc; v.y *= sc; v.z *= sc; v.w *= sc;
        o4[i] = v;
    }
}

// t[v][b][i*64+o] = sum_e feats_v[b,i,e] * W_v[i,o,e]
__global__ void __launch_bounds__(256) tfield_kernel(const float* __restrict__ x,
                                                     const float* __restrict__ W1,
                                                     const float* __restrict__ W2) {
    __shared__ float Ws[64 * 68];
    __shared__ float xs[16 * 68];
    __shared__ float ts[1024];
    int v = blockIdx.z, fi = blockIdx.x, b0 = blockIdx.y * 16;
    int tid = threadIdx.x;
    const float* W = (v ? W2 : W1) + (size_t)fi * 4096;
    for (int idx = tid; idx < 4096; idx += 256)
        Ws[(idx >> 6) * 68 + (idx & 63)] = W[idx];
    const float* xsrc = (v ? g_x2 : x) + (size_t)b0 * X_LD + fi * 64;
    for (int idx = tid; idx < 1024; idx += 256)
        xs[(idx >> 6) * 68 + (idx & 63)] = xsrc[(size_t)(idx >> 6) * X_LD + (idx & 63)];
    __syncthreads();
    int o = tid >> 2, bg = tid & 3;
    float s0 = 0.f, s1 = 0.f, s2 = 0.f, s3 = 0.f;
    const float4* wrow = (const float4*)(Ws + o * 68);
    #pragma unroll
    for (int e4 = 0; e4 < 16; e4++) {
        float4 wv = wrow[e4];
        float4 a0 = *(const float4*)(xs + (bg * 4 + 0) * 68 + e4 * 4);
        float4 a1 = *(const float4*)(xs + (bg * 4 + 1) * 68 + e4 * 4);
        float4 a2 = *(const float4*)(xs + (bg * 4 + 2) * 68 + e4 * 4);
        float4 a3 = *(const float4*)(xs + (bg * 4 + 3) * 68 + e4 * 4);
        s0 += wv.x*a0.x + wv.y*a0.y + wv.z*a0.z + wv.w*a0.w;
        s1 += wv.x*a1.x + wv.y*a1.y + wv.z*a1.z + wv.w*a1.w;
        s2 += wv.x*a2.x + wv.y*a2.y + wv.z*a2.z + wv.w*a2.w;
        s3 += wv.x*a3.x + wv.y*a3.y + wv.z*a3.z + wv.w*a3.w;
    }
    ts[(bg * 4 + 0) * 64 + o] = s0;
    ts[(bg * 4 + 1) * 64 + o] = s1;
    ts[(bg * 4 + 2) * 64 + o] = s2;
    ts[(bg * 4 + 3) * 64 + o] = s3;
    __syncthreads();
    float* trow = g_T + (size_t)v * (BATCH * T_LD);
    for (int idx = tid; idx < 1024; idx += 256)
        trow[(size_t)(b0 + (idx >> 6)) * T_LD + fi * 64 + (idx & 63)] = ts[idx];
}

// ---------------- fused prep: featgen + fc0 weight f2h + fc1 weight f2h ----------------
#define PREP_FEAT   31744
#define PREP_W0     63488
#define PREP_W1B    512
__global__ void __launch_bounds__(256) prep_kernel(const float* __restrict__ x,
                                                   const float* __restrict__ fc0w,
                                                   const float* __restrict__ fc1w) {
    int blk = blockIdx.x;
    int tid = threadIdx.x;
    if (blk < PREP_FEAT) {
        int p = blk % NPAIR;
        int rest = blk / NPAIR;        // 0..63
        int b0 = (rest & 31) * 32;
        int v = rest >> 5;
        int r = tid >> 3, ec = (tid & 7) * 8;
        int ip = g_pi[p], jp = g_pj[p];
        int b = b0 + r;
        const float* tb = g_T + (size_t)v * (BATCH * T_LD) + (size_t)b * T_LD + ip * 64 + ec;
        const float* xb = (v ? g_x2 : x) + (size_t)b * X_LD + jp * 64 + ec;
        float4 t0 = *(const float4*)tb, t1 = *(const float4*)(tb + 4);
        float4 x0 = *(const float4*)xb, x1 = *(const float4*)(xb + 4);
        uint4 o;
        o.x = pack_h2(t0.x * x0.x, t0.y * x0.y);
        o.y = pack_h2(t0.z * x0.z, t0.w * x0.w);
        o.z = pack_h2(t1.x * x1.x, t1.y * x1.y);
        o.w = pack_h2(t1.z * x1.z, t1.w * x1.w);
        *(uint4*)(g_feat + (size_t)b * KTOT + v * HALFK + p * 64 + ec) = o;
    } else if (blk < PREP_FEAT + PREP_W0) {
        int i = (blk - PREP_FEAT) * 256 + tid;
        float4 v = ((const float4*)fc0w)[i];
        uint2 o;
        o.x = pack_h2(v.x, v.y);
        o.y = pack_h2(v.z, v.w);
        ((uint2*)g_w0h)[i] = o;
    } else {
        int i = (blk - PREP_FEAT - PREP_W0) * 256 + tid;
        float4 v = ((const float4*)fc1w)[i];
        uint2 o;
        o.x = pack_h2(v.x, v.y);
        o.y = pack_h2(v.z, v.w);
        ((uint2*)g_w1h)[i] = o;
    }
}

// ---------------- mma.sync fp16 GEMM (BK=64, 2-stage cp.async) ----------------
// C[m,n] = sum_k A[m,k] * W[n,k]; A, W fp16 row-major with row stride Ktot.
// CTA decode: mb fastest, then nb, then s -> one s-group's CTAs co-resident in L2.
__global__ void __launch_bounds__(256, 2) gemm_kernel(const __half* __restrict__ Ah,
                                                      const __half* __restrict__ Bw,
                                                      float* __restrict__ Cpart,
                                                      int Ntot, int Ktot, int S) {
    extern __shared__ char smc[];
    uint32_t smb = smem_u32(smc);
    int tid = threadIdx.x;
    int w = tid >> 5, l = tid & 31;
    int wr = w >> 2, wc = w & 3;
    int nbn = Ntot >> 7;
    int mb = blockIdx.x % 8;
    int nb = (blockIdx.x / 8) % nbn;
    int s  = blockIdx.x / (8 * nbn);
    int m0 = mb * 128, n0 = nb * 128;
    int Kper = Ktot / S;
    int k_base = s * Kper;
    int ntiles = Kper >> 6;

    int cr = tid >> 2, cq = tid & 3;   // cp.async: rows cr, cr+64; 16B chunks cq, cq+4

    float acc[4][4][4];
    #pragma unroll
    for (int i = 0; i < 4; i++)
        #pragma unroll
        for (int j = 0; j < 4; j++)
            #pragma unroll
            for (int q = 0; q < 4; q++) acc[i][j][q] = 0.f;

    auto cp_tile = [&](int kg, int st) {
        uint32_t baseA = smb + st * 2 * TBUFH_BYTES;
        uint32_t baseB = baseA + TBUFH_BYTES;
        #pragma unroll
        for (int it = 0; it < 2; it++) {
            int r = cr + it * 64;
            const __half* arow = Ah + (size_t)(m0 + r) * Ktot + kg;
            const __half* brow = Bw + (size_t)(n0 + r) * Ktot + kg;
            uint32_t dA = baseA + r * SROWB;
            uint32_t dB = baseB + r * SROWB;
            #pragma unroll
            for (int c = 0; c < 2; c++) {
                int ch = cq + c * 4;
                cp_async16(dA + ch * 16, arow + ch * 8);
                cp_async16(dB + ch * 16, brow + ch * 8);
            }
        }
    };

    cp_tile(k_base, 0);
    CP_COMMIT();

    int mlane = l >> 2, klane = l & 3;
    for (int kt = 0; kt < ntiles; kt++) {
        int st = kt & 1;
        CP_WAIT0();
        __syncthreads();
        if (kt + 1 < ntiles) {
            cp_tile(k_base + ((kt + 1) << 6), st ^ 1);
            CP_COMMIT();
        }

        const uint32_t* uA = (const uint32_t*)(smc + st * 2 * TBUFH_BYTES);
        const uint32_t* uB = (const uint32_t*)(smc + st * 2 * TBUFH_BYTES + TBUFH_BYTES);
        #pragma unroll
        for (int ks = 0; ks < 4; ks++) {
            int kw = ks * 8 + klane;
            uint32_t afr[4][4], bfr[4][2];
            #pragma unroll
            for (int mf = 0; mf < 4; mf++) {
                int m = wr * 64 + mf * 16 + mlane;
                afr[mf][0] = uA[m * 36 + kw];
                afr[mf][1] = uA[(m + 8) * 36 + kw];
                afr[mf][2] = uA[m * 36 + kw + 4];
                afr[mf][3] = uA[(m + 8) * 36 + kw + 4];
            }
            #pragma unroll
            for (int nf = 0; nf < 4; nf++) {
                int n = wc * 32 + nf * 8 + mlane;
                bfr[nf][0] = uB[n * 36 + kw];
                bfr[nf][1] = uB[n * 36 + kw + 4];
            }
            #pragma unroll
            for (int mf = 0; mf < 4; mf++)
                #pragma unroll
                for (int nf = 0; nf < 4; nf++)
                    mma_f16(acc[mf][nf], afr[mf], bfr[nf]);
        }
    }

    float* crow = Cpart + ((size_t)s * BATCH + m0 + wr * 64) * Ntot + n0 + wc * 32;
    #pragma unroll
    for (int mf = 0; mf < 4; mf++) {
        int mm = mf * 16 + (l >> 2);
        #pragma unroll
        for (int nf = 0; nf < 4; nf++) {
            int nn = nf * 8 + (l & 3) * 2;
            *(float2*)(crow + (size_t)mm * Ntot + nn) = make_float2(acc[mf][nf][0], acc[mf][nf][1]);
            *(float2*)(crow + (size_t)(mm + 8) * Ntot + nn) = make_float2(acc[mf][nf][2], acc[mf][nf][3]);
        }
    }
}

// ---------------- reductions / final ----------------
__global__ void __launch_bounds__(256) reduce0_kernel(const float* __restrict__ bias) {
    int f = blockIdx.x * 256 + threadIdx.x;   // float4 index, 262144 total
    const float4* p = (const float4*)g_part0;
    float4 b = ((const float4*)bias)[f & 255];
    float sx = b.x, sy = b.y, sz = b.z, sw = b.w;
    #pragma unroll
    for (int i = 0; i < S0; i++) {
        float4 a = p[f + (size_t)i * 262144];
        sx += a.x; sy += a.y; sz += a.z; sw += a.w;
    }
    uint2 o;
    o.x = pack_h2(fmaxf(sx, 0.f), fmaxf(sy, 0.f));
    o.y = pack_h2(fmaxf(sz, 0.f), fmaxf(sw, 0.f));
    ((uint2*)g_h0h)[f] = o;
}

__global__ void __launch_bounds__(256) reduce1_kernel(const float* __restrict__ bias) {
    int f = blockIdx.x * 256 + threadIdx.x;   // float4 index, 131072 total
    const float4* p = (const float4*)g_part1;
    float4 b = ((const float4*)bias)[f & 127];
    float sx = b.x, sy = b.y, sz = b.z, sw = b.w;
    #pragma unroll
    for (int i = 0; i < S1; i++) {
        float4 a = p[f + (size_t)i * 131072];
        sx += a.x; sy += a.y; sz += a.z; sw += a.w;
    }
    float4 o;
    o.x = fmaxf(sx, 0.f); o.y = fmaxf(sy, 0.f);
    o.z = fmaxf(sz, 0.f); o.w = fmaxf(sw, 0.f);
    ((float4*)g_h1)[f] = o;
}

__global__ void __launch_bounds__(256) fc2_kernel(const float* __restrict__ w,
                                                  const float* __restrict__ bias,
                                                  float* __restrict__ out) {
    int wid = threadIdx.x >> 5, lane = threadIdx.x & 31;
    int row = blockIdx.x * 8 + wid;
    const float4* h = (const float4*)(g_h1 + (size_t)row * H2);
    const float4* wv = (const float4*)w;
    float s = 0.f;
    #pragma unroll
    for (int q = 0; q < 4; q++) {
        float4 a = h[lane + q * 32], b = wv[lane + q * 32];
        s += a.x * b.x + a.y * b.y + a.z * b.z + a.w * b.w;
    }
    #pragma unroll
    for (int o = 16; o; o >>= 1) s += __shfl_xor_sync(0xffffffffu, s, o);
    if (lane == 0) out[row] = 1.0f / (1.0f + expf(-(s + bias[0])));
}

// ---------------- launch ----------------
extern "C" void kernel_launch(void* const* d_in, const int* in_sizes, int n_in,
                              void* d_out, int out_size) {
    const float* x    = (const float*)d_in[0];
    const float* W1   = (const float*)d_in[1];
    const float* W2   = (const float*)d_in[2];
    const float* sw1  = (const float*)d_in[3];
    const float* sw2  = (const float*)d_in[4];
    const float* fc0w = (const float*)d_in[5];
    const float* fc0b = (const float*)d_in[6];
    const float* fc1w = (const float*)d_in[7];
    const float* fc1b = (const float*)d_in[8];
    const float* fc2w = (const float*)d_in[9];
    const float* fc2b = (const float*)d_in[10];
    float* out = (float*)d_out;

    __half* w0h;  cudaGetSymbolAddress((void**)&w0h, g_w0h);
    __half* w1h;  cudaGetSymbolAddress((void**)&w1h, g_w1h);
    __half* feat; cudaGetSymbolAddress((void**)&feat, g_feat);
    __half* h0h;  cudaGetSymbolAddress((void**)&h0h, g_h0h);
    float* part0; cudaGetSymbolAddress((void**)&part0, g_part0);
    float* part1; cudaGetSymbolAddress((void**)&part1, g_part1);

    cudaFuncSetAttribute(gemm_kernel, cudaFuncAttributeMaxDynamicSharedMemorySize, SMEM_DYN);

    se_kernel<<<BATCH + 1, 256>>>(x, sw1, sw2);                      // #1 (+pair init)
    tfield_kernel<<<dim3(31, BATCH / 16, 2), 256>>>(x, W1, W2);      // #2
    prep_kernel<<<PREP_FEAT + PREP_W0 + PREP_W1B, 256>>>(x, fc0w, fc1w); // #3
    gemm_kernel<<<8 * 8 * S0, 256, SMEM_DYN>>>(feat, w0h, part0, H1, KTOT, S0); // #4 <- profiled
    reduce0_kernel<<<1024, 256>>>(fc0b);
    gemm_kernel<<<8 * 4 * S1, 256, SMEM_DYN>>>(h0h, w1h, part1, H2, H1, S1);
    reduce1_kernel<<<512, 256>>>(fc1b);
    fc2_kernel<<<BATCH / 8, 256>>>(fc2w, fc2b, out);
}